// round 14
// baseline (speedup 1.0000x reference)
#include <cuda_runtime.h>

// LengthRegulator v8 (R14 = infra retry of R13, kernel unchanged):
// v6's two-kernel split + v7's shared-tile back half.
//
//  K1 (32 CTAs x 1024): row cumsum -> g_cs (coalesced int4), per-1024-window
//     start token (register-resident boundary detection, unique writer),
//     g_total[b].
//  K2 (32*nblk CTAs x 256, 4KB smem): ZERO setup — read t0/total, zero a
//     1024-wide tile, ONE strided-token round of coalesced cs LDGs, scatter
//     runs into tile, coalesced copy-out. High occupancy hides L2 latency.
//
// Evidence: v7 (8.0us) = scan+16KB load per 512 CTAs then fast tile scatter;
// v6 fill (9.5us) = no setup but uncoalesced gmem scatter. v8 combines the
// fast halves of each.

#define N_TOK       4096
#define B_ROWS      32
#define WIN         1024                 // output window per K2 CTA
#define MAX_WIN     64
#define K2_THREADS  256

__device__ int g_cs[B_ROWS * N_TOK];         // inclusive cumsum per row
__device__ int g_start[B_ROWS * MAX_WIN];    // first token intersecting window
__device__ int g_total[B_ROWS];              // row totals

// ---------------- K1: cumsum + window starts ----------------
__global__ __launch_bounds__(1024, 1)
void lr_v8_cumsum(const int* __restrict__ dur, int nblk) {
    const int b    = blockIdx.x;
    const int tid  = threadIdx.x;
    const int lane = tid & 31;
    const int wid  = tid >> 5;

    __shared__ int s_wsum[32];
    __shared__ int s_woff[33];

    // init window starts (before any sync; detection writes happen after syncs)
    if (tid < MAX_WIN) g_start[b * MAX_WIN + tid] = N_TOK;

    // 4 tokens per thread
    int4 d = ((const int4*)(dur + b * N_TOK))[tid];
    const int c0 = d.x;
    const int c1 = c0 + d.y;
    const int c2 = c1 + d.z;
    const int c3 = c2 + d.w;
    const int my_total = c3;

    // warp scan of thread totals
    int s = my_total;
    #pragma unroll
    for (int o = 1; o < 32; o <<= 1) {
        int u = __shfl_up_sync(0xffffffffu, s, o);
        if (lane >= o) s += u;
    }
    if (lane == 31) s_wsum[wid] = s;
    __syncthreads();

    if (wid == 0) {
        int vv = s_wsum[lane];
        #pragma unroll
        for (int o = 1; o < 32; o <<= 1) {
            int u = __shfl_up_sync(0xffffffffu, vv, o);
            if (lane >= o) vv += u;
        }
        s_woff[lane + 1] = vv;
        if (lane == 0) s_woff[0] = 0;
    }
    __syncthreads();

    const int base = s_woff[wid] + (s - my_total);
    if (tid == 0) g_total[b] = s_woff[32];

    // inclusive cumsum, coalesced int4
    int4 cs4;
    cs4.x = base + c0; cs4.y = base + c1; cs4.z = base + c2; cs4.w = base + c3;
    ((int4*)(g_cs + b * N_TOK))[tid] = cs4;

    // boundary detection: run [st,en) (len<16) contains boundary w*WIN iff
    // st <= w*WIN < en; at most one w per run (WIN >> 16); unique writer.
    const int tok0 = tid << 2;
    int stv[4] = { base,      base + c0, base + c1, base + c2 };
    int env[4] = { base + c0, base + c1, base + c2, base + c3 };
    #pragma unroll
    for (int i = 0; i < 4; i++) {
        const int st = stv[i], en = env[i];
        if (en > st) {
            const int w = (st + WIN - 1) / WIN;          // ceil(st / WIN)
            if (w < nblk && w * WIN < en)
                g_start[b * MAX_WIN + w] = tok0 + i;
        }
    }
}

// ---------------- K2: window fill via shared tile ----------------
__global__ __launch_bounds__(K2_THREADS)
void lr_v8_fill(float* __restrict__ out, int T, int nblk) {
    const int b     = blockIdx.x / nblk;
    const int chunk = blockIdx.x % nblk;
    const int tid   = threadIdx.x;

    __shared__ float s_out[WIN];

    const int p0    = chunk * WIN;
    const int p_end = (p0 + WIN < T) ? p0 + WIN : T;

    // issue broadcast loads early (L2 latency overlapped with tile zeroing)
    const int t0    = g_start[b * MAX_WIN + chunk];
    const int total = g_total[b];

    // zero tile: covers tail [total, p_end) and any unwritten slots
    #pragma unroll
    for (int k = 0; k < WIN / K2_THREADS; k++)
        s_out[k * K2_THREADS + tid] = 0.0f;
    __syncthreads();

    int p1 = (p_end < total) ? p_end : total;

    // scatter: tokens strided across threads from t0; cs loads coalesced.
    const int* cs = g_cs + b * N_TOK;
    if (p0 < p1) {
        for (int t = t0 + tid; t < N_TOK; t += K2_THREADS) {
            const int st = (t == 0) ? 0 : cs[t - 1];
            if (st >= p1) break;                  // cs monotone: safe per-thread
            int en = cs[t];
            if (en > p1) en = p1;
            const float val = (float)(t + 1);
            for (int p = (st > p0 ? st : p0); p < en; p++)
                s_out[p - p0] = val;
        }
    }
    __syncthreads();

    // coalesced copy-out (scalar: row base not 16B-aligned for general T)
    float* orow = out + b * T;
    #pragma unroll
    for (int k = 0; k < WIN / K2_THREADS; k++) {
        const int idx = k * K2_THREADS + tid;
        const int p   = p0 + idx;
        if (p < T) orow[p] = s_out[idx];
    }
}

extern "C" void kernel_launch(void* const* d_in, const int* in_sizes, int n_in,
                              void* d_out, int out_size) {
    const int* dur = (const int*)d_in[0];
    float*     out = (float*)d_out;
    const int  T    = out_size / B_ROWS;
    int nblk = (T + WIN - 1) / WIN;
    if (nblk > MAX_WIN) nblk = MAX_WIN;   // T <= 15*4096 -> nblk <= 60

    lr_v8_cumsum<<<B_ROWS, 1024>>>(dur, nblk);
    lr_v8_fill<<<B_ROWS * nblk, K2_THREADS>>>(out, T, nblk);
}